// round 2
// baseline (speedup 1.0000x reference)
#include <cuda_runtime.h>
#include <cuda_bf16.h>
#include <math.h>

#define NHID 128
#define NODE_CAP 100000
#define EDGE_GRID 2048

constexpr int NT   = 64;    // nodes per block (kernel 1)
constexpr int PADW = 132;   // padded row length for W smem [256][PADW]
constexpr int PADF = 68;    // padded row length for F^T smem [128][PADF]

// Scratch (device globals: allocation inside kernel_launch is forbidden)
__device__ float g_ptop[(size_t)NODE_CAP * NHID];   // feature @ W1[:128]
__device__ float g_pbot[(size_t)NODE_CAP * NHID];   // feature @ W1[128:]
__device__ float g_partial[EDGE_GRID];
__device__ int   g_is64;

// ---------------------------------------------------------------------------
// Kernel 0: sniff index dtype. If data is int64 (values < 1e5), every odd
// 32-bit word is zero. With int32 data, 32 consecutive odd words being zero
// has probability ~0.
// ---------------------------------------------------------------------------
__global__ void detect_idx_kernel(const unsigned int* __restrict__ p, int n_elems) {
    if (threadIdx.x == 0 && blockIdx.x == 0) {
        int nchk = n_elems >= 64 ? 64 : n_elems;
        int is64 = 1;
        for (int i = 0; i < nchk; i++) {
            if (p[2 * i + 1] != 0u) { is64 = 0; break; }
        }
        g_is64 = is64;
    }
}

// ---------------------------------------------------------------------------
// Kernel 1: per-node projections.
//   P_top[n][o] = sum_k F[n][k] * W1[k][o]
//   P_bot[n][o] = sum_k F[n][k] * W1[128+k][o]
// Block: 256 threads, 64 nodes, 256 outputs (128 top + 128 bot).
// Thread (tr=tid&7, tc=tid>>3): 8 nodes x 8 outputs register microtile.
// ---------------------------------------------------------------------------
__global__ void node_proj_kernel(const float* __restrict__ feature,
                                 const float* __restrict__ W1,
                                 int n_nodes) {
    extern __shared__ float sm[];
    float* Wsh = sm;                       // [256][PADW]
    float* Fsh = sm + 256 * PADW;          // [128][PADF]  (F transposed: [k][n_local])

    const int tid   = threadIdx.x;
    const int nbase = blockIdx.x * NT;

    // Stage W1 (256x128) as-is, padded rows.
    for (int idx = tid; idx < 256 * NHID; idx += blockDim.x) {
        int j = idx >> 7;          // input row 0..255
        int o = idx & 127;         // output col
        Wsh[j * PADW + o] = W1[idx];
    }
    // Stage feature tile transposed: Fsh[k][nl]
    for (int idx = tid; idx < NT * NHID; idx += blockDim.x) {
        int nl = idx >> 7;
        int k  = idx & 127;
        int n  = nbase + nl;
        float v = (n < n_nodes) ? feature[(size_t)n * NHID + k] : 0.0f;
        Fsh[k * PADF + nl] = v;
    }
    __syncthreads();

    const int tr   = tid & 7;            // node-group 0..7
    const int tc   = tid >> 3;           // output-group 0..31
    const int half = tc >> 4;            // 0 = top, 1 = bot
    const int ob   = (tc & 15) * 8;      // output base within 128
    const int n0   = tr * 8;
    const int koff = half * 128;

    float acc[8][8];
    #pragma unroll
    for (int i = 0; i < 8; i++)
        #pragma unroll
        for (int j = 0; j < 8; j++) acc[i][j] = 0.0f;

    #pragma unroll 4
    for (int k = 0; k < NHID; k++) {
        float4 fA = *(const float4*)&Fsh[k * PADF + n0];
        float4 fB = *(const float4*)&Fsh[k * PADF + n0 + 4];
        const float* wrow = &Wsh[(k + koff) * PADW + ob];
        float4 wA = *(const float4*)(wrow);
        float4 wB = *(const float4*)(wrow + 4);
        float f[8] = {fA.x, fA.y, fA.z, fA.w, fB.x, fB.y, fB.z, fB.w};
        float w[8] = {wA.x, wA.y, wA.z, wA.w, wB.x, wB.y, wB.z, wB.w};
        #pragma unroll
        for (int i = 0; i < 8; i++)
            #pragma unroll
            for (int j = 0; j < 8; j++)
                acc[i][j] = fmaf(f[i], w[j], acc[i][j]);
    }

    float* dst = half ? g_pbot : g_ptop;
    #pragma unroll
    for (int i = 0; i < 8; i++) {
        int n = nbase + n0 + i;
        if (n < n_nodes) {
            float4 o1 = make_float4(acc[i][0], acc[i][1], acc[i][2], acc[i][3]);
            float4 o2 = make_float4(acc[i][4], acc[i][5], acc[i][6], acc[i][7]);
            *(float4*)&dst[(size_t)n * NHID + ob]     = o1;
            *(float4*)&dst[(size_t)n * NHID + ob + 4] = o2;
        }
    }
}

// ---------------------------------------------------------------------------
// Kernel 2: per-edge loss, warp-per-edge (grid-stride over edges).
// Each lane owns 4 channels (lane*4 .. lane*4+3) -> perfectly coalesced
// 512B gathers from g_ptop[r] / g_pbot[c].
// ---------------------------------------------------------------------------
__global__ void __launch_bounds__(256) edge_loss_kernel(
        const void* __restrict__ row_p,
        const void* __restrict__ col_p,
        const void* __restrict__ label_p,
        const float* __restrict__ b1,
        const float* __restrict__ alpha,
        const float* __restrict__ W2,
        const float* __restrict__ b2,
        int n_edges) {
    const int lane = threadIdx.x & 31;
    const int wid  = threadIdx.x >> 5;
    const int warps_per_block = blockDim.x >> 5;
    const int warp_global = blockIdx.x * warps_per_block + wid;
    const int nwarps = gridDim.x * warps_per_block;
    const int base = lane * 4;

    const int is64 = g_is64;
    const long long* __restrict__ row64 = (const long long*)row_p;
    const long long* __restrict__ col64 = (const long long*)col_p;
    const long long* __restrict__ lab64 = (const long long*)label_p;
    const int* __restrict__ row32 = (const int*)row_p;
    const int* __restrict__ col32 = (const int*)col_p;
    const int* __restrict__ lab32 = (const int*)label_p;

    // Per-lane constants (loop-invariant)
    const float4 b1v = *(const float4*)&b1[base];
    const float4 al  = *(const float4*)&alpha[base];
    const float4 w2a = *(const float4*)&W2[base * 2];      // (c0w0,c0w1,c1w0,c1w1)
    const float4 w2b = *(const float4*)&W2[base * 2 + 4];  // (c2w0,c2w1,c3w0,c3w1)
    const float b20 = b2[0], b21 = b2[1];

    float lsum = 0.0f;

    for (int e = warp_global; e < n_edges; e += nwarps) {
        long long r, c, lr, lc;
        if (is64) {
            r = row64[e]; c = col64[e];
            lr = lab64[r]; lc = lab64[c];
        } else {
            r = row32[e]; c = col32[e];
            lr = lab32[r]; lc = lab32[c];
        }
        const int y = (lr == lc) ? 1 : 0;

        const float4 a = *(const float4*)&g_ptop[r * NHID + base];
        const float4 b = *(const float4*)&g_pbot[c * NHID + base];

        float hx = a.x + b.x + b1v.x;
        float hy = a.y + b.y + b1v.y;
        float hz = a.z + b.z + b1v.z;
        float hw = a.w + b.w + b1v.w;
        hx = (hx >= 0.0f) ? hx : al.x * hx;
        hy = (hy >= 0.0f) ? hy : al.y * hy;
        hz = (hz >= 0.0f) ? hz : al.z * hz;
        hw = (hw >= 0.0f) ? hw : al.w * hw;

        float u = hx * w2a.x + hy * w2a.z + hz * w2b.x + hw * w2b.z;
        float v = hx * w2a.y + hy * w2a.w + hz * w2b.y + hw * w2b.w;

        #pragma unroll
        for (int off = 16; off > 0; off >>= 1) {
            u += __shfl_xor_sync(0xffffffffu, u, off);
            v += __shfl_xor_sync(0xffffffffu, v, off);
        }
        u += b20;
        v += b21;

        const float m   = fmaxf(u, v);
        const float lse = m + logf(expf(u - m) + expf(v - m));
        const float le  = lse - (y ? v : u);
        if (lane == 0) lsum += le;
    }

    __shared__ float ssum[8];
    if (lane == 0) ssum[wid] = lsum;
    __syncthreads();
    if (threadIdx.x == 0) {
        float s = 0.0f;
        for (int i = 0; i < warps_per_block; i++) s += ssum[i];
        g_partial[blockIdx.x] = s;
    }
}

// ---------------------------------------------------------------------------
// Kernel 3: deterministic final reduction.
// ---------------------------------------------------------------------------
__global__ void finalize_kernel(float* __restrict__ out, int nblocks, float inv_e) {
    __shared__ double sd[256];
    double s = 0.0;
    for (int i = threadIdx.x; i < nblocks; i += blockDim.x) s += (double)g_partial[i];
    sd[threadIdx.x] = s;
    __syncthreads();
    for (int off = 128; off > 0; off >>= 1) {
        if (threadIdx.x < off) sd[threadIdx.x] += sd[threadIdx.x + off];
        __syncthreads();
    }
    if (threadIdx.x == 0) out[0] = (float)(sd[0] * (double)inv_e);
}

// ---------------------------------------------------------------------------
// Launch
// Inputs (metadata order): feature, W1, b1, alpha, W2, b2, row, col, label
// ---------------------------------------------------------------------------
extern "C" void kernel_launch(void* const* d_in, const int* in_sizes, int n_in,
                              void* d_out, int out_size) {
    const float* feature = (const float*)d_in[0];
    const float* W1      = (const float*)d_in[1];
    const float* b1      = (const float*)d_in[2];
    const float* alpha   = (const float*)d_in[3];
    const float* W2      = (const float*)d_in[4];
    const float* b2      = (const float*)d_in[5];
    const void*  row     = d_in[6];
    const void*  col     = d_in[7];
    const void*  label   = d_in[8];
    float* out = (float*)d_out;

    const int n_nodes = in_sizes[0] / NHID;
    const int n_edges = in_sizes[6];

    const size_t smem = (size_t)(256 * PADW + 128 * PADF) * sizeof(float); // 169,984 B
    cudaFuncSetAttribute(node_proj_kernel,
                         cudaFuncAttributeMaxDynamicSharedMemorySize, (int)smem);

    detect_idx_kernel<<<1, 32>>>((const unsigned int*)row, n_edges);

    node_proj_kernel<<<(n_nodes + NT - 1) / NT, 256, smem>>>(feature, W1, n_nodes);

    edge_loss_kernel<<<EDGE_GRID, 256>>>(row, col, label, b1, alpha, W2, b2, n_edges);

    finalize_kernel<<<1, 256>>>(out, EDGE_GRID, 1.0f / (float)n_edges);
}

// round 4
// speedup vs baseline: 1.1063x; 1.1063x over previous
#include <cuda_runtime.h>
#include <cuda_fp16.h>
#include <mma.h>
#include <math.h>

using namespace nvcuda;

#define NHID 128
#define NODE_CAP 100000
#define EDGE_GRID 1184          // 8 blocks/SM on 148 SMs

constexpr int PADA = 136;       // padded stride (floats) for 128-wide smem tiles
constexpr int PSTG = 72;        // padded stride for 32x64 staging tiles

// Scratch (device globals: allocation inside kernel_launch is forbidden)
// Combined projection table: g_proj[n][0:128] = ptop[n], g_proj[n][128:256] = pbot[n]
__device__ __half g_proj[(size_t)NODE_CAP * 256];
__device__ float  g_partial[EDGE_GRID];
__device__ int    g_is64;
__device__ unsigned int g_done;

// ---------------------------------------------------------------------------
// Kernel 0: sniff index dtype (int64 values < 1e5 -> every odd 32-bit word 0)
// and reset the last-block counter.
// ---------------------------------------------------------------------------
__global__ void detect_idx_kernel(const unsigned int* __restrict__ p, int n_elems) {
    if (threadIdx.x == 0 && blockIdx.x == 0) {
        g_done = 0u;
        int nchk = n_elems >= 64 ? 64 : n_elems;
        int is64 = 1;
        for (int i = 0; i < nchk; i++) {
            if (p[2 * i + 1] != 0u) { is64 = 0; break; }
        }
        g_is64 = is64;
    }
}

// ---------------------------------------------------------------------------
// Kernel 1: per-node projections via tf32 WMMA.
//   P[n][o'] = sum_k F[n][k] * W1[128*blockIdx.y + k][o'-128*blockIdx.y ... ]
// Block tile: 128 nodes x 128 outputs, K=128. 8 warps (4 M-tiles x 2 N-tiles),
// warp tile 32x64 = 2x4 wmma 16x16x8 fragments.
// ---------------------------------------------------------------------------
__global__ void __launch_bounds__(256) node_proj_kernel(
        const float* __restrict__ feature,
        const float* __restrict__ W1,
        int n_nodes) {
    extern __shared__ float sm[];
    float* Ash = sm;                   // [128][PADA]  nodes x k
    float* Bsh = sm + 128 * PADA;      // [128][PADA]  k x out(128)

    const int tid   = threadIdx.x;
    const int nbase = blockIdx.x * 128;
    // blockIdx.y = 0 -> top half of W1 (rows 0..127), 1 -> bottom half (rows 128..255)
    const float* Wbase = W1 + (size_t)blockIdx.y * 128 * 128;

    for (int idx = tid; idx < 128 * 128; idx += 256) {
        int r = idx >> 7, c = idx & 127;
        int n = nbase + r;
        Ash[r * PADA + c] = (n < n_nodes) ? feature[(size_t)n * 128 + c] : 0.0f;
        Bsh[r * PADA + c] = Wbase[idx];
    }
    __syncthreads();

    const int w    = tid >> 5;
    const int lane = tid & 31;
    const int wm   = w & 3;        // 32-row tile index
    const int wn   = w >> 2;       // 64-col tile index

    wmma::fragment<wmma::accumulator, 16, 16, 8, float> acc[2][4];
    #pragma unroll
    for (int i = 0; i < 2; i++)
        #pragma unroll
        for (int j = 0; j < 4; j++)
            wmma::fill_fragment(acc[i][j], 0.0f);

    #pragma unroll
    for (int k0 = 0; k0 < 128; k0 += 8) {
        wmma::fragment<wmma::matrix_a, 16, 16, 8, wmma::precision::tf32, wmma::row_major> a[2];
        wmma::fragment<wmma::matrix_b, 16, 16, 8, wmma::precision::tf32, wmma::row_major> b[4];
        #pragma unroll
        for (int i = 0; i < 2; i++) {
            wmma::load_matrix_sync(a[i], &Ash[(wm * 32 + i * 16) * PADA + k0], PADA);
            #pragma unroll
            for (int t = 0; t < a[i].num_elements; t++)
                a[i].x[t] = wmma::__float_to_tf32(a[i].x[t]);
        }
        #pragma unroll
        for (int j = 0; j < 4; j++) {
            wmma::load_matrix_sync(b[j], &Bsh[k0 * PADA + wn * 64 + j * 16], PADA);
            #pragma unroll
            for (int t = 0; t < b[j].num_elements; t++)
                b[j].x[t] = wmma::__float_to_tf32(b[j].x[t]);
        }
        #pragma unroll
        for (int i = 0; i < 2; i++)
            #pragma unroll
            for (int j = 0; j < 4; j++)
                wmma::mma_sync(acc[i][j], a[i], b[j], acc[i][j]);
    }

    __syncthreads();   // done with Ash/Bsh; reuse as per-warp staging

    float* stage = sm + w * (32 * PSTG);   // 32x64 (stride PSTG) per warp
    #pragma unroll
    for (int i = 0; i < 2; i++)
        #pragma unroll
        for (int j = 0; j < 4; j++)
            wmma::store_matrix_sync(&stage[(i * 16) * PSTG + j * 16], acc[i][j],
                                    PSTG, wmma::mem_row_major);
    __syncwarp();

    const int obase = blockIdx.y * 128 + wn * 64;
    #pragma unroll 4
    for (int r = 0; r < 32; r++) {
        int n = nbase + wm * 32 + r;
        if (n < n_nodes) {
            float2 f = *(const float2*)&stage[r * PSTG + lane * 2];
            __half2 hv = __floats2half2_rn(f.x, f.y);
            *(__half2*)&g_proj[(size_t)n * 256 + obase + lane * 2] = hv;
        }
    }
}

// ---------------------------------------------------------------------------
// Kernel 2: per-edge loss, warp-per-edge. Lane owns 4 channels (lane*4..+3):
// 8B fp16 gathers, split-warp u/v reduction (7 shfls), softplus loss.
// Final reduction fused via deterministic last-block pattern.
// ---------------------------------------------------------------------------
__global__ void __launch_bounds__(256) edge_loss_kernel(
        const void* __restrict__ row_p,
        const void* __restrict__ col_p,
        const void* __restrict__ label_p,
        const float* __restrict__ b1,
        const float* __restrict__ alpha,
        const float* __restrict__ W2,
        const float* __restrict__ b2,
        float* __restrict__ out,
        int n_edges) {
    const int lane = threadIdx.x & 31;
    const int wid  = threadIdx.x >> 5;
    const int warp_global = blockIdx.x * 8 + wid;
    const int nwarps = gridDim.x * 8;
    const int base = lane * 4;

    const int is64 = g_is64;
    const long long* __restrict__ row64 = (const long long*)row_p;
    const long long* __restrict__ col64 = (const long long*)col_p;
    const long long* __restrict__ lab64 = (const long long*)label_p;
    const int* __restrict__ row32 = (const int*)row_p;
    const int* __restrict__ col32 = (const int*)col_p;
    const int* __restrict__ lab32 = (const int*)label_p;

    // Per-lane constants
    const float4 b1v = *(const float4*)&b1[base];
    const float4 al  = *(const float4*)&alpha[base];
    const float4 w2a = *(const float4*)&W2[base * 2];      // (c0w0,c0w1,c1w0,c1w1)
    const float4 w2b = *(const float4*)&W2[base * 2 + 4];  // (c2w0,c2w1,c3w0,c3w1)
    const float b20 = b2[0], b21 = b2[1];

    float lsum = 0.0f;

    for (int e = warp_global; e < n_edges; e += nwarps) {
        long long r, c, lr, lc;
        if (is64) {
            r = row64[e]; c = col64[e];
            lr = lab64[r]; lc = lab64[c];
        } else {
            r = row32[e]; c = col32[e];
            lr = lab32[r]; lc = lab32[c];
        }
        const int y = (lr == lc) ? 1 : 0;

        // 8B fp16 gathers (4 channels per lane)
        float2 pa = *(const float2*)&g_proj[r * 256 + base];          // ptop
        float2 pb = *(const float2*)&g_proj[c * 256 + 128 + base];    // pbot
        __half2 a01 = *(__half2*)&pa.x, a23 = *(__half2*)&pa.y;
        __half2 b01 = *(__half2*)&pb.x, b23 = *(__half2*)&pb.y;
        float2 fa01 = __half22float2(a01), fa23 = __half22float2(a23);
        float2 fb01 = __half22float2(b01), fb23 = __half22float2(b23);

        float hx = fa01.x + fb01.x + b1v.x;
        float hy = fa01.y + fb01.y + b1v.y;
        float hz = fa23.x + fb23.x + b1v.z;
        float hw = fa23.y + fb23.y + b1v.w;
        hx = (hx >= 0.0f) ? hx : al.x * hx;
        hy = (hy >= 0.0f) ? hy : al.y * hy;
        hz = (hz >= 0.0f) ? hz : al.z * hz;
        hw = (hw >= 0.0f) ? hw : al.w * hw;

        float u = hx * w2a.x + hy * w2a.z + hz * w2b.x + hw * w2b.z;
        float v = hx * w2a.y + hy * w2a.w + hz * w2b.y + hw * w2b.w;

        // Split-warp dual reduction: lanes 0-15 accumulate u, 16-31 accumulate v.
        float s = (lane < 16) ? u : v;
        float o = (lane < 16) ? v : u;
        s += __shfl_xor_sync(0xffffffffu, o, 16);
        #pragma unroll
        for (int off = 8; off > 0; off >>= 1)
            s += __shfl_xor_sync(0xffffffffu, s, off);
        // lanes 0-15: total u; lanes 16-31: total v
        float vt = __shfl_sync(0xffffffffu, s, 16);
        if (lane == 0) {
            float ut = s + b20;
            vt += b21;
            // loss = lse(u,v) - logit_y = softplus(l_other - l_y)
            float d = y ? (ut - vt) : (vt - ut);
            lsum += fmaxf(d, 0.0f) + log1pf(__expf(-fabsf(d)));
        }
    }

    __shared__ float ssum[8];
    __shared__ bool  s_last;
    if (lane == 0) ssum[wid] = lsum;
    __syncthreads();
    if (threadIdx.x == 0) {
        float s = 0.0f;
        #pragma unroll
        for (int i = 0; i < 8; i++) s += ssum[i];
        g_partial[blockIdx.x] = s;
        __threadfence();
        unsigned int prev = atomicAdd(&g_done, 1u);
        s_last = (prev == gridDim.x - 1);
    }
    __syncthreads();

    if (s_last) {
        // Deterministic final reduction in the last block.
        __shared__ double sd[256];
        const volatile float* gp = g_partial;
        double acc = 0.0;
        for (int i = threadIdx.x; i < (int)gridDim.x; i += 256) acc += (double)gp[i];
        sd[threadIdx.x] = acc;
        __syncthreads();
        for (int off = 128; off > 0; off >>= 1) {
            if (threadIdx.x < off) sd[threadIdx.x] += sd[threadIdx.x + off];
            __syncthreads();
        }
        if (threadIdx.x == 0) out[0] = (float)(sd[0] / (double)n_edges);
    }
}

// ---------------------------------------------------------------------------
// Launch. Inputs: feature, W1, b1, alpha, W2, b2, row, col, label
// ---------------------------------------------------------------------------
extern "C" void kernel_launch(void* const* d_in, const int* in_sizes, int n_in,
                              void* d_out, int out_size) {
    const float* feature = (const float*)d_in[0];
    const float* W1      = (const float*)d_in[1];
    const float* b1      = (const float*)d_in[2];
    const float* alpha   = (const float*)d_in[3];
    const float* W2      = (const float*)d_in[4];
    const float* b2      = (const float*)d_in[5];
    const void*  row     = d_in[6];
    const void*  col     = d_in[7];
    const void*  label   = d_in[8];
    float* out = (float*)d_out;

    const int n_nodes = in_sizes[0] / NHID;
    const int n_edges = in_sizes[6];

    const size_t smem = (size_t)(2 * 128 * PADA) * sizeof(float);  // 139,264 B
    cudaFuncSetAttribute(node_proj_kernel,
                         cudaFuncAttributeMaxDynamicSharedMemorySize, (int)smem);

    detect_idx_kernel<<<1, 32>>>((const unsigned int*)row, n_edges);

    dim3 pg((n_nodes + 127) / 128, 2);
    node_proj_kernel<<<pg, 256, smem>>>(feature, W1, n_nodes);

    edge_loss_kernel<<<EDGE_GRID, 256>>>(row, col, label, b1, alpha, W2, b2,
                                         out, n_edges);
}

// round 5
// speedup vs baseline: 2.0906x; 1.8897x over previous
#include <cuda_runtime.h>
#include <cuda_fp16.h>
#include <mma.h>
#include <math.h>

using namespace nvcuda;

#define NHID 128
#define NODE_CAP 100000
#define EDGE_GRID 1184

constexpr int PADH = 136;   // half-element stride for 128-wide fp16 smem tiles
constexpr int PSTG = 72;    // float stride for 32x64 epilogue staging

// Scratch (device globals; allocation in kernel_launch is forbidden)
// g_proj[n][0:128] = F@W1_top + b1 (fp16), g_proj[n][128:256] = F@W1_bot (fp16)
__device__ __half g_proj[(size_t)NODE_CAP * 256];
__device__ float  g_partial[EDGE_GRID];
__device__ uint2  g_cd[64];        // per channel-pair: {wp=half2(wd), wn=half2(alpha*wd)}
__device__ float  g_db;            // b2[0] - b2[1]
__device__ int    g_is64;
__device__ unsigned int g_done;

static __device__ __forceinline__ __half2 u2h2(unsigned int u) {
    __half2 h; *(unsigned int*)&h = u; return h;
}

// ---------------------------------------------------------------------------
// Kernel 0: fused setup. Detect index dtype, reset counter, build the
// edge-phase channel constant table: wd[c] = W2[c][0]-W2[c][1],
// wp2 = half2(wd pair), wn2 = half2(alpha*wd pair).
// ---------------------------------------------------------------------------
__global__ void setup_kernel(const unsigned int* __restrict__ rowp, int n_edges,
                             const float* __restrict__ W2,
                             const float* __restrict__ alpha,
                             const float* __restrict__ b2) {
    int t = threadIdx.x;
    if (t < 64) {
        float wd0 = W2[4 * t + 0] - W2[4 * t + 1];
        float wd1 = W2[4 * t + 2] - W2[4 * t + 3];
        __half2 wp = __floats2half2_rn(wd0, wd1);
        __half2 wn = __floats2half2_rn(alpha[2 * t] * wd0, alpha[2 * t + 1] * wd1);
        uint2 cd;
        cd.x = *(unsigned int*)&wp;
        cd.y = *(unsigned int*)&wn;
        g_cd[t] = cd;
    }
    if (t == 0) {
        g_done = 0u;
        g_db = b2[0] - b2[1];
        int nchk = n_edges >= 64 ? 64 : n_edges;
        int is64 = 1;
        for (int i = 0; i < nchk; i++)
            if (rowp[2 * i + 1] != 0u) { is64 = 0; break; }
        g_is64 = is64;
    }
}

// ---------------------------------------------------------------------------
// Kernel 1: node projections via fp16 WMMA (m16n16k16).
// Block: 128 nodes x 128 outputs, K=128, 8 warps (4M x 2N), warp tile 32x64.
// blockIdx.y selects W1 half (0: rows 0..127 -> ptop (+b1), 1: rows 128..255 -> pbot).
// ---------------------------------------------------------------------------
__global__ void __launch_bounds__(256, 2) node_proj_kernel(
        const float* __restrict__ feature,
        const float* __restrict__ W1,
        const float* __restrict__ b1,
        int n_nodes) {
    extern __shared__ float sm[];
    __half* Ah = (__half*)sm;                 // [128][PADH] nodes x k
    __half* Bh = Ah + 128 * PADH;             // [128][PADH] k x out
    float*  stage = sm;                       // reused after compute

    const int tid   = threadIdx.x;
    const int nbase = blockIdx.x * 128;
    const float* Wbase = W1 + (size_t)blockIdx.y * 128 * 128;

    for (int idx = tid; idx < 128 * 64; idx += 256) {
        int r  = idx >> 6;
        int c2 = (idx & 63) * 2;
        int n  = nbase + r;
        float2 fa = (n < n_nodes) ? *(const float2*)&feature[(size_t)n * 128 + c2]
                                  : make_float2(0.0f, 0.0f);
        *(__half2*)&Ah[r * PADH + c2] = __floats2half2_rn(fa.x, fa.y);
        float2 fb = *(const float2*)&Wbase[r * 128 + c2];
        *(__half2*)&Bh[r * PADH + c2] = __floats2half2_rn(fb.x, fb.y);
    }
    __syncthreads();

    const int w    = tid >> 5;
    const int lane = tid & 31;
    const int wm   = w & 3;        // 32-row M tile
    const int wn   = w >> 2;       // 64-col N tile

    wmma::fragment<wmma::accumulator, 16, 16, 16, float> acc[2][4];
    #pragma unroll
    for (int i = 0; i < 2; i++)
        #pragma unroll
        for (int j = 0; j < 4; j++)
            wmma::fill_fragment(acc[i][j], 0.0f);

    #pragma unroll
    for (int k0 = 0; k0 < 128; k0 += 16) {
        wmma::fragment<wmma::matrix_a, 16, 16, 16, __half, wmma::row_major> a[2];
        #pragma unroll
        for (int i = 0; i < 2; i++)
            wmma::load_matrix_sync(a[i], &Ah[(wm * 32 + i * 16) * PADH + k0], PADH);
        #pragma unroll
        for (int j = 0; j < 4; j++) {
            wmma::fragment<wmma::matrix_b, 16, 16, 16, __half, wmma::row_major> b;
            wmma::load_matrix_sync(b, &Bh[k0 * PADH + wn * 64 + j * 16], PADH);
            #pragma unroll
            for (int i = 0; i < 2; i++)
                wmma::mma_sync(acc[i][j], a[i], b, acc[i][j]);
        }
    }

    __syncthreads();   // done with Ah/Bh; reuse smem as per-warp fp32 staging

    float* ws = stage + w * (32 * PSTG);
    #pragma unroll
    for (int i = 0; i < 2; i++)
        #pragma unroll
        for (int j = 0; j < 4; j++)
            wmma::store_matrix_sync(&ws[(i * 16) * PSTG + j * 16], acc[i][j],
                                    PSTG, wmma::mem_row_major);
    __syncwarp();

    // epilogue: +b1 for the top half, convert to fp16, write g_proj
    const int co    = lane * 2;
    const int obase = blockIdx.y * 128 + wn * 64;
    float2 bv = make_float2(0.0f, 0.0f);
    if (blockIdx.y == 0) bv = *(const float2*)&b1[wn * 64 + co];

    #pragma unroll 4
    for (int r = 0; r < 32; r++) {
        int n = nbase + wm * 32 + r;
        if (n < n_nodes) {
            float2 f = *(const float2*)&ws[r * PSTG + co];
            *(__half2*)&g_proj[(size_t)n * 256 + obase + co] =
                __floats2half2_rn(f.x + bv.x, f.y + bv.y);
        }
    }
}

// ---------------------------------------------------------------------------
// Kernel 2: per-edge loss, 4 threads per edge (quad). Thread q handles
// channels [q*32, q*32+32): 64B LDG.128 gathers from ptop[r] and pbot[c],
// fp16x2 PReLU-dot against precomputed (wp, wn), 2 shfls to combine,
// softplus loss. Deterministic last-block final reduction.
// ---------------------------------------------------------------------------
__global__ void __launch_bounds__(256) edge_loss_kernel(
        const void* __restrict__ row_p,
        const void* __restrict__ col_p,
        const void* __restrict__ label_p,
        float* __restrict__ out,
        int n_edges) {
    __shared__ uint2 s_cd[64];
    if (threadIdx.x < 64) s_cd[threadIdx.x] = g_cd[threadIdx.x];
    __syncthreads();

    const int q  = threadIdx.x & 3;        // quad position
    const int hb = q * 32;                 // channel base (halves)
    const int gq = (blockIdx.x * blockDim.x + threadIdx.x) >> 2;
    const int nq = (gridDim.x * blockDim.x) >> 2;

    const int is64 = g_is64;
    const float db = g_db;
    const long long* __restrict__ row64 = (const long long*)row_p;
    const long long* __restrict__ col64 = (const long long*)col_p;
    const long long* __restrict__ lab64 = (const long long*)label_p;
    const int* __restrict__ row32 = (const int*)row_p;
    const int* __restrict__ col32 = (const int*)col_p;
    const int* __restrict__ lab32 = (const int*)label_p;

    const __half2 z2 = __floats2half2_rn(0.0f, 0.0f);
    float lsum = 0.0f;

    for (int e = gq; e < n_edges; e += nq) {
        long long r, c, lr, lc;
        if (is64) {
            r = row64[e]; c = col64[e];
            lr = lab64[r]; lc = lab64[c];
        } else {
            r = row32[e]; c = col32[e];
            lr = lab32[r]; lc = lab32[c];
        }
        const int y = (lr == lc) ? 1 : 0;

        const uint4* pt = (const uint4*)(g_proj + r * 256 + hb);
        const uint4* pc = (const uint4*)(g_proj + c * 256 + 128 + hb);

        float acc0 = 0.0f, acc1 = 0.0f;
        #pragma unroll
        for (int i = 0; i < 4; i++) {
            uint4 A = pt[i];
            uint4 B = pc[i];
            __half2 acch = z2;
            const unsigned int au[4] = {A.x, A.y, A.z, A.w};
            const unsigned int bu[4] = {B.x, B.y, B.z, B.w};
            #pragma unroll
            for (int j = 0; j < 4; j++) {
                __half2 t  = __hadd2(u2h2(au[j]), u2h2(bu[j]));
                __half2 mx = __hmax2(t, z2);
                __half2 mn = __hmin2(t, z2);
                uint2 cd = s_cd[q * 16 + i * 4 + j];
                acch = __hfma2(u2h2(cd.x), mx, acch);
                acch = __hfma2(u2h2(cd.y), mn, acch);
            }
            float2 f = __half22float2(acch);
            acc0 += f.x;
            acc1 += f.y;
        }

        float d0 = acc0 + acc1;
        d0 += __shfl_xor_sync(0xffffffffu, d0, 1);
        d0 += __shfl_xor_sync(0xffffffffu, d0, 2);
        if (q == 0) {
            float d = y ? (d0 + db) : -(d0 + db);
            lsum += fmaxf(d, 0.0f) + log1pf(__expf(-fabsf(d)));
        }
    }

    // block reduction (quad leaders only hold nonzero lsum)
    #pragma unroll
    for (int off = 16; off > 0; off >>= 1)
        lsum += __shfl_xor_sync(0xffffffffu, lsum, off);

    __shared__ float ssum[8];
    __shared__ bool  s_last;
    const int wid  = threadIdx.x >> 5;
    const int lane = threadIdx.x & 31;
    if (lane == 0) ssum[wid] = lsum;
    __syncthreads();
    if (threadIdx.x == 0) {
        float s = 0.0f;
        #pragma unroll
        for (int i = 0; i < 8; i++) s += ssum[i];
        g_partial[blockIdx.x] = s;
        __threadfence();
        unsigned int prev = atomicAdd(&g_done, 1u);
        s_last = (prev == gridDim.x - 1);
    }
    __syncthreads();

    if (s_last) {
        __shared__ double sd[256];
        const volatile float* gp = g_partial;
        double acc = 0.0;
        for (int i = threadIdx.x; i < (int)gridDim.x; i += 256) acc += (double)gp[i];
        sd[threadIdx.x] = acc;
        __syncthreads();
        for (int off = 128; off > 0; off >>= 1) {
            if (threadIdx.x < off) sd[threadIdx.x] += sd[threadIdx.x + off];
            __syncthreads();
        }
        if (threadIdx.x == 0) out[0] = (float)(sd[0] / (double)n_edges);
    }
}

// ---------------------------------------------------------------------------
// Launch. Inputs: feature, W1, b1, alpha, W2, b2, row, col, label
// ---------------------------------------------------------------------------
extern "C" void kernel_launch(void* const* d_in, const int* in_sizes, int n_in,
                              void* d_out, int out_size) {
    const float* feature = (const float*)d_in[0];
    const float* W1      = (const float*)d_in[1];
    const float* b1      = (const float*)d_in[2];
    const float* alpha   = (const float*)d_in[3];
    const float* W2      = (const float*)d_in[4];
    const float* b2      = (const float*)d_in[5];
    const void*  row     = d_in[6];
    const void*  col     = d_in[7];
    const void*  label   = d_in[8];
    float* out = (float*)d_out;

    const int n_nodes = in_sizes[0] / NHID;
    const int n_edges = in_sizes[6];

    const size_t smem = (size_t)(8 * 32 * PSTG) * sizeof(float);  // 73,728 B
    cudaFuncSetAttribute(node_proj_kernel,
                         cudaFuncAttributeMaxDynamicSharedMemorySize, (int)smem);

    setup_kernel<<<1, 64>>>((const unsigned int*)row, n_edges, W2, alpha, b2);

    dim3 pg((n_nodes + 127) / 128, 2);
    node_proj_kernel<<<pg, 256, smem>>>(feature, W1, b1, n_nodes);

    edge_loss_kernel<<<EDGE_GRID, 256>>>(row, col, label, out, n_edges);
}

// round 7
// speedup vs baseline: 2.4440x; 1.1691x over previous
#include <cuda_runtime.h>
#include <cuda_fp16.h>
#include <mma.h>
#include <math.h>

using namespace nvcuda;

#define NHID 128
#define NODE_CAP 100000
#define EDGE_GRID 1184

constexpr int PADH = 136;   // half stride for A tile [64][128+8]
constexpr int PADB = 264;   // half stride for B tile [128][256+8]
constexpr int PSTG = 72;    // float stride for 32x64 epilogue staging

// Scratch (device globals; allocation in kernel_launch is forbidden)
// g_proj[n][0:128] = F@W1_top + b1 (fp16), g_proj[n][128:256] = F@W1_bot (fp16)
__device__ __half g_proj[(size_t)NODE_CAP * 256];
__device__ __half g_w1h[128 * 256];   // fp16 W1, concat layout: [k][o<128:top | o>=128:bot]
__device__ float  g_partial[EDGE_GRID];
__device__ uint2  g_cd[64];           // per channel-pair: {half2(wd), half2(alpha*wd)}
__device__ float  g_db;               // b2[0] - b2[1]
__device__ int    g_is64;
__device__ unsigned int g_done;

static __device__ __forceinline__ __half2 u2h2(unsigned int u) {
    __half2 h; *(unsigned int*)&h = u; return h;
}

// ---------------------------------------------------------------------------
// Kernel 0: setup. Convert W1 -> fp16 concat layout (all blocks), and in
// block 0: detect index dtype, build edge-phase constants, reset counter.
// Grid: 64 blocks x 256 threads (16384 threads = one half2 each).
// ---------------------------------------------------------------------------
__global__ void setup_kernel(const unsigned int* __restrict__ rowp, int n_edges,
                             const float* __restrict__ W1,
                             const float* __restrict__ W2,
                             const float* __restrict__ alpha,
                             const float* __restrict__ b2) {
    const int gid = blockIdx.x * 256 + threadIdx.x;   // [0, 16384)
    const int k   = gid >> 7;
    const int o2  = (gid & 127) * 2;                  // even, pair stays in one half
    float2 f = (o2 < 128) ? *(const float2*)&W1[k * 128 + o2]
                          : *(const float2*)&W1[(128 + k) * 128 + (o2 - 128)];
    *(__half2*)&g_w1h[k * 256 + o2] = __floats2half2_rn(f.x, f.y);

    if (blockIdx.x == 0) {
        int t = threadIdx.x;
        if (t < 64) {
            float wd0 = W2[4 * t + 0] - W2[4 * t + 1];
            float wd1 = W2[4 * t + 2] - W2[4 * t + 3];
            __half2 wp = __floats2half2_rn(wd0, wd1);
            __half2 wn = __floats2half2_rn(alpha[2 * t] * wd0, alpha[2 * t + 1] * wd1);
            uint2 cd;
            cd.x = *(unsigned int*)&wp;
            cd.y = *(unsigned int*)&wn;
            g_cd[t] = cd;
        }
        if (t == 0) {
            g_done = 0u;
            g_db = b2[0] - b2[1];
            int nchk = n_edges >= 64 ? 64 : n_edges;
            int is64 = 1;
            for (int i = 0; i < nchk; i++)
                if (rowp[2 * i + 1] != 0u) { is64 = 0; break; }
            g_is64 = is64;
        }
    }
}

// ---------------------------------------------------------------------------
// Kernel 1: node projections, single pass. Block: 64 nodes x 256 outputs,
// K=128, fp16 WMMA m16n16k16. 8 warps: wm = w&1 (32-row tile), wn = w>>1
// (64-col tile). B staged from pre-converted g_w1h (fp16, straight copy).
// ---------------------------------------------------------------------------
__global__ void __launch_bounds__(256, 2) node_proj_kernel(
        const float* __restrict__ feature,
        const float* __restrict__ b1,
        int n_nodes) {
    extern __shared__ float sm[];
    __half* Ah = (__half*)sm;             // [64][PADH]
    __half* Bh = Ah + 64 * PADH;          // [128][PADB]

    const int tid   = threadIdx.x;
    const int nbase = blockIdx.x * 64;

    // Stage A: 64 nodes x 128 k (fp32 -> fp16), 4096 half2 / 256 thr = 16 each
    for (int idx = tid; idx < 64 * 64; idx += 256) {
        int r  = idx >> 6;
        int c2 = (idx & 63) * 2;
        int n  = nbase + r;
        float2 fa = (n < n_nodes) ? *(const float2*)&feature[(size_t)n * 128 + c2]
                                  : make_float2(0.0f, 0.0f);
        *(__half2*)&Ah[r * PADH + c2] = __floats2half2_rn(fa.x, fa.y);
    }
    // Stage B: straight uint4 copy of g_w1h (128 x 32 uint4)
    {
        const uint4* src = (const uint4*)g_w1h;
        uint4* dst = (uint4*)Bh;
        for (int idx = tid; idx < 128 * 32; idx += 256) {
            int k  = idx >> 5;
            int cu = idx & 31;
            dst[k * (PADB / 8) + cu] = src[k * 32 + cu];
        }
    }
    __syncthreads();

    const int w    = tid >> 5;
    const int lane = tid & 31;
    const int wm   = w & 1;        // 32-row M tile (0..1)
    const int wn   = w >> 1;       // 64-col N tile (0..3)

    wmma::fragment<wmma::accumulator, 16, 16, 16, float> acc[2][4];
    #pragma unroll
    for (int i = 0; i < 2; i++)
        #pragma unroll
        for (int j = 0; j < 4; j++)
            wmma::fill_fragment(acc[i][j], 0.0f);

    #pragma unroll
    for (int k0 = 0; k0 < 128; k0 += 16) {
        wmma::fragment<wmma::matrix_a, 16, 16, 16, __half, wmma::row_major> a[2];
        #pragma unroll
        for (int i = 0; i < 2; i++)
            wmma::load_matrix_sync(a[i], &Ah[(wm * 32 + i * 16) * PADH + k0], PADH);
        #pragma unroll
        for (int j = 0; j < 4; j++) {
            wmma::fragment<wmma::matrix_b, 16, 16, 16, __half, wmma::row_major> b;
            wmma::load_matrix_sync(b, &Bh[k0 * PADB + wn * 64 + j * 16], PADB);
            #pragma unroll
            for (int i = 0; i < 2; i++)
                wmma::mma_sync(acc[i][j], a[i], b, acc[i][j]);
        }
    }

    __syncthreads();   // reuse smem as per-warp fp32 staging

    float* ws = sm + w * (32 * PSTG);
    #pragma unroll
    for (int i = 0; i < 2; i++)
        #pragma unroll
        for (int j = 0; j < 4; j++)
            wmma::store_matrix_sync(&ws[(i * 16) * PSTG + j * 16], acc[i][j],
                                    PSTG, wmma::mem_row_major);
    __syncwarp();

    // epilogue: +b1 on outputs < 128, convert, store
    const int co    = lane * 2;
    const int obase = wn * 64;
    const int ob    = obase + co;
    float2 bv = (ob < 128) ? *(const float2*)&b1[ob] : make_float2(0.0f, 0.0f);

    #pragma unroll 4
    for (int r = 0; r < 32; r++) {
        int n = nbase + wm * 32 + r;
        if (n < n_nodes) {
            float2 f = *(const float2*)&ws[r * PSTG + co];
            *(__half2*)&g_proj[(size_t)n * 256 + ob] =
                __floats2half2_rn(f.x + bv.x, f.y + bv.y);
        }
    }
}

// ---------------------------------------------------------------------------
// Kernel 2: per-edge loss, quad (4 threads) per edge, software-pipelined
// index/label loads, warp-uniform trip count, fp16x2 PReLU-dot,
// softplus loss, deterministic last-block final reduction.
// ---------------------------------------------------------------------------
__global__ void __launch_bounds__(256) edge_loss_kernel(
        const void* __restrict__ row_p,
        const void* __restrict__ col_p,
        const void* __restrict__ label_p,
        float* __restrict__ out,
        int n_edges) {
    __shared__ uint2 s_cd[64];
    if (threadIdx.x < 64) s_cd[threadIdx.x] = g_cd[threadIdx.x];
    __syncthreads();

    const int lane = threadIdx.x & 31;
    const int q    = threadIdx.x & 3;          // quad position
    const int hb   = q * 32;                   // channel base (halves)
    const int gq   = (blockIdx.x * blockDim.x + threadIdx.x) >> 2;
    const int nq   = (gridDim.x * blockDim.x) >> 2;

    const int is64 = g_is64;
    const float db = g_db;
    const long long* __restrict__ row64 = (const long long*)row_p;
    const long long* __restrict__ col64 = (const long long*)col_p;
    const long long* __restrict__ lab64 = (const long long*)label_p;
    const int* __restrict__ row32 = (const int*)row_p;
    const int* __restrict__ col32 = (const int*)col_p;
    const int* __restrict__ lab32 = (const int*)label_p;

    // warp-uniform trip count (first quad in warp defines it)
    const int gq0   = gq - (lane >> 2);
    const int trips = (gq0 < n_edges) ? (n_edges - gq0 + nq - 1) / nq : 0;

    const __half2 z2 = __floats2half2_rn(0.0f, 0.0f);
    float lsum = 0.0f;

    int e = gq;
    bool v = (e < n_edges);
    int ri = 0, ci = 0, yy = 0;
    {
        int es = v ? e : 0;
        if (is64) {
            long long r = row64[es], c = col64[es];
            ri = (int)r; ci = (int)c;
            yy = (lab64[r] == lab64[c]);
        } else {
            ri = row32[es]; ci = col32[es];
            yy = (lab32[ri] == lab32[ci]);
        }
    }

    for (int t = 0; t < trips; t++) {
        // prefetch next iteration's indices + labels
        int en = e + nq;
        bool vn = (en < n_edges);
        int ri2 = 0, ci2 = 0, yy2 = 0;
        {
            int es = vn ? en : 0;
            if (is64) {
                long long r = row64[es], c = col64[es];
                ri2 = (int)r; ci2 = (int)c;
                yy2 = (lab64[r] == lab64[c]);
            } else {
                ri2 = row32[es]; ci2 = col32[es];
                yy2 = (lab32[ri2] == lab32[ci2]);
            }
        }

        const uint4* pt = (const uint4*)(g_proj + (size_t)ri * 256 + hb);
        const uint4* pc = (const uint4*)(g_proj + (size_t)ci * 256 + 128 + hb);

        float acc0 = 0.0f, acc1 = 0.0f;
        #pragma unroll
        for (int i = 0; i < 4; i++) {
            uint4 A = pt[i];
            uint4 B = pc[i];
            __half2 acch = z2;
            const unsigned int au[4] = {A.x, A.y, A.z, A.w};
            const unsigned int bu[4] = {B.x, B.y, B.z, B.w};
            #pragma unroll
            for (int j = 0; j < 4; j++) {
                __half2 h  = __hadd2(u2h2(au[j]), u2h2(bu[j]));
                __half2 mx = __hmax2(h, z2);
                __half2 mn = __hmin2(h, z2);
                uint2 cd = s_cd[q * 16 + i * 4 + j];
                acch = __hfma2(u2h2(cd.x), mx, acch);
                acch = __hfma2(u2h2(cd.y), mn, acch);
            }
            float2 f = __half22float2(acch);
            acc0 += f.x;
            acc1 += f.y;
        }

        float d0 = acc0 + acc1;
        d0 += __shfl_xor_sync(0xffffffffu, d0, 1);
        d0 += __shfl_xor_sync(0xffffffffu, d0, 2);
        if (q == 0 && v) {
            float d = yy ? (d0 + db) : -(d0 + db);
            lsum += fmaxf(d, 0.0f) + log1pf(__expf(-fabsf(d)));
        }

        ri = ri2; ci = ci2; yy = yy2; v = vn; e = en;
    }

    // block reduction (only q==0 lanes hold nonzero lsum)
    #pragma unroll
    for (int off = 16; off > 0; off >>= 1)
        lsum += __shfl_xor_sync(0xffffffffu, lsum, off);

    __shared__ float ssum[8];
    __shared__ bool  s_last;
    const int wid = threadIdx.x >> 5;
    if (lane == 0) ssum[wid] = lsum;
    __syncthreads();
    if (threadIdx.x == 0) {
        float s = 0.0f;
        #pragma unroll
        for (int i = 0; i < 8; i++) s += ssum[i];
        g_partial[blockIdx.x] = s;
        __threadfence();
        unsigned int prev = atomicAdd(&g_done, 1u);
        s_last = (prev == gridDim.x - 1);
    }
    __syncthreads();

    if (s_last) {
        __shared__ double sd[256];
        const volatile float* gp = g_partial;
        double acc = 0.0;
        for (int i = threadIdx.x; i < (int)gridDim.x; i += 256) acc += (double)gp[i];
        sd[threadIdx.x] = acc;
        __syncthreads();
        for (int off = 128; off > 0; off >>= 1) {
            if (threadIdx.x < off) sd[threadIdx.x] += sd[threadIdx.x + off];
            __syncthreads();
        }
        if (threadIdx.x == 0) out[0] = (float)(sd[0] / (double)n_edges);
    }
}

// ---------------------------------------------------------------------------
// Launch. Inputs: feature, W1, b1, alpha, W2, b2, row, col, label
// ---------------------------------------------------------------------------
extern "C" void kernel_launch(void* const* d_in, const int* in_sizes, int n_in,
                              void* d_out, int out_size) {
    const float* feature = (const float*)d_in[0];
    const float* W1      = (const float*)d_in[1];
    const float* b1      = (const float*)d_in[2];
    const float* alpha   = (const float*)d_in[3];
    const float* W2      = (const float*)d_in[4];
    const float* b2      = (const float*)d_in[5];
    const void*  row     = d_in[6];
    const void*  col     = d_in[7];
    const void*  label   = d_in[8];
    float* out = (float*)d_out;

    const int n_nodes = in_sizes[0] / NHID;
    const int n_edges = in_sizes[6];

    // smem: A (64*PADH) + B (128*PADB) halves = 84,992 B (epilogue reuses it)
    const size_t smem = (size_t)(64 * PADH + 128 * PADB) * sizeof(__half);
    cudaFuncSetAttribute(node_proj_kernel,
                         cudaFuncAttributeMaxDynamicSharedMemorySize, (int)smem);

    setup_kernel<<<64, 256>>>((const unsigned int*)row, n_edges, W1, W2, alpha, b2);

    node_proj_kernel<<<(n_nodes + 63) / 64, 256, smem>>>(feature, b1, n_nodes);

    edge_loss_kernel<<<EDGE_GRID, 256>>>(row, col, label, out, n_edges);
}

// round 13
// speedup vs baseline: 2.9003x; 1.1867x over previous
#include <cuda_runtime.h>
#include <cuda_fp16.h>
#include <mma.h>
#include <math.h>

using namespace nvcuda;

#define NHID 128
#define NODE_CAP 100000
#define EDGE_GRID 592

constexpr int PADH = 136;   // half stride for A tile [64][128+8]
constexpr int PADB = 264;   // half stride for B tile [128][256+8]
constexpr int PSTG = 72;    // float stride for 32x64 epilogue staging

// Scratch (device globals; allocation in kernel_launch is forbidden)
// g_proj[n][0:128] = F@W1_top + b1 (fp16), g_proj[n][128:256] = F@W1_bot (fp16)
__device__ __half g_proj[(size_t)NODE_CAP * 256];
__device__ __half g_w1h[128 * 256];   // fp16 W1, concat layout
__device__ float  g_partial[EDGE_GRID];
__device__ uint2  g_cd[64];           // per channel-pair: {half2(wd), half2(alpha*wd)}
__device__ float  g_db;               // b2[0] - b2[1]
__device__ int    g_is64;
__device__ unsigned int g_done;

static __device__ __forceinline__ __half2 u2h2(unsigned int u) {
    __half2 h; *(unsigned int*)&h = u; return h;
}

// ---------------------------------------------------------------------------
// Kernel 0: setup. Convert W1 -> fp16 concat layout; block 0 also detects
// index dtype, builds edge-phase constants, resets counter.
// ---------------------------------------------------------------------------
__global__ void setup_kernel(const unsigned int* __restrict__ rowp, int n_edges,
                             const float* __restrict__ W1,
                             const float* __restrict__ W2,
                             const float* __restrict__ alpha,
                             const float* __restrict__ b2) {
    const int gid = blockIdx.x * 256 + threadIdx.x;   // [0, 16384)
    const int k   = gid >> 7;
    const int o2  = (gid & 127) * 2;
    float2 f = (o2 < 128) ? *(const float2*)&W1[k * 128 + o2]
                          : *(const float2*)&W1[(128 + k) * 128 + (o2 - 128)];
    *(__half2*)&g_w1h[k * 256 + o2] = __floats2half2_rn(f.x, f.y);

    if (blockIdx.x == 0) {
        int t = threadIdx.x;
        if (t < 64) {
            float wd0 = W2[4 * t + 0] - W2[4 * t + 1];
            float wd1 = W2[4 * t + 2] - W2[4 * t + 3];
            __half2 wp = __floats2half2_rn(wd0, wd1);
            __half2 wn = __floats2half2_rn(alpha[2 * t] * wd0, alpha[2 * t + 1] * wd1);
            uint2 cd;
            cd.x = *(unsigned int*)&wp;
            cd.y = *(unsigned int*)&wn;
            g_cd[t] = cd;
        }
        if (t == 0) {
            g_done = 0u;
            g_db = b2[0] - b2[1];
            int nchk = n_edges >= 64 ? 64 : n_edges;
            int is64 = 1;
            for (int i = 0; i < nchk; i++)
                if (rowp[2 * i + 1] != 0u) { is64 = 0; break; }
            g_is64 = is64;
        }
    }
}

// ---------------------------------------------------------------------------
// Kernel 1: node projections, single pass. Block: 64 nodes x 256 outputs,
// K=128, fp16 WMMA m16n16k16.
// ---------------------------------------------------------------------------
__global__ void __launch_bounds__(256, 2) node_proj_kernel(
        const float* __restrict__ feature,
        const float* __restrict__ b1,
        int n_nodes) {
    extern __shared__ float sm[];
    __half* Ah = (__half*)sm;             // [64][PADH]
    __half* Bh = Ah + 64 * PADH;          // [128][PADB]

    const int tid   = threadIdx.x;
    const int nbase = blockIdx.x * 64;

    for (int idx = tid; idx < 64 * 64; idx += 256) {
        int r  = idx >> 6;
        int c2 = (idx & 63) * 2;
        int n  = nbase + r;
        float2 fa = (n < n_nodes) ? *(const float2*)&feature[(size_t)n * 128 + c2]
                                  : make_float2(0.0f, 0.0f);
        *(__half2*)&Ah[r * PADH + c2] = __floats2half2_rn(fa.x, fa.y);
    }
    {
        const uint4* src = (const uint4*)g_w1h;
        uint4* dst = (uint4*)Bh;
        for (int idx = tid; idx < 128 * 32; idx += 256) {
            int k  = idx >> 5;
            int cu = idx & 31;
            dst[k * (PADB / 8) + cu] = src[k * 32 + cu];
        }
    }
    __syncthreads();

    const int w    = tid >> 5;
    const int lane = tid & 31;
    const int wm   = w & 1;
    const int wn   = w >> 1;

    wmma::fragment<wmma::accumulator, 16, 16, 16, float> acc[2][4];
    #pragma unroll
    for (int i = 0; i < 2; i++)
        #pragma unroll
        for (int j = 0; j < 4; j++)
            wmma::fill_fragment(acc[i][j], 0.0f);

    #pragma unroll
    for (int k0 = 0; k0 < 128; k0 += 16) {
        wmma::fragment<wmma::matrix_a, 16, 16, 16, __half, wmma::row_major> a[2];
        #pragma unroll
        for (int i = 0; i < 2; i++)
            wmma::load_matrix_sync(a[i], &Ah[(wm * 32 + i * 16) * PADH + k0], PADH);
        #pragma unroll
        for (int j = 0; j < 4; j++) {
            wmma::fragment<wmma::matrix_b, 16, 16, 16, __half, wmma::row_major> b;
            wmma::load_matrix_sync(b, &Bh[k0 * PADB + wn * 64 + j * 16], PADB);
            #pragma unroll
            for (int i = 0; i < 2; i++)
                wmma::mma_sync(acc[i][j], a[i], b, acc[i][j]);
        }
    }

    __syncthreads();

    float* ws = sm + w * (32 * PSTG);
    #pragma unroll
    for (int i = 0; i < 2; i++)
        #pragma unroll
        for (int j = 0; j < 4; j++)
            wmma::store_matrix_sync(&ws[(i * 16) * PSTG + j * 16], acc[i][j],
                                    PSTG, wmma::mem_row_major);
    __syncwarp();

    const int co = lane * 2;
    const int ob = wn * 64 + co;
    float2 bv = (ob < 128) ? *(const float2*)&b1[ob] : make_float2(0.0f, 0.0f);

    #pragma unroll 4
    for (int r = 0; r < 32; r++) {
        int n = nbase + wm * 32 + r;
        if (n < n_nodes) {
            float2 f = *(const float2*)&ws[r * PSTG + co];
            *(__half2*)&g_proj[(size_t)n * 256 + ob] =
                __floats2half2_rn(f.x + bv.x, f.y + bv.y);
        }
    }
}

// ---------------------------------------------------------------------------
// Kernel 2: per-edge loss. 8 threads per edge (octet), 2 edges per octet per
// iteration (8 independent LDG.128 per thread-iteration). Thread o handles
// channel halves [o*16, o*16+16). Prefetched idx/label pipeline, warp-uniform
// trips, fp16x2 PReLU-dot, softplus loss, last-block final reduction.
// ---------------------------------------------------------------------------
__global__ void __launch_bounds__(256) edge_loss_kernel(
        const void* __restrict__ row_p,
        const void* __restrict__ col_p,
        const void* __restrict__ label_p,
        float* __restrict__ out,
        int n_edges) {
    __shared__ uint2 s_cd[64];
    if (threadIdx.x < 64) s_cd[threadIdx.x] = g_cd[threadIdx.x];
    __syncthreads();

    const int lane = threadIdx.x & 31;
    const int o    = threadIdx.x & 7;          // octet position
    const int hb   = o * 16;                   // channel base (halves)
    const int go   = (blockIdx.x * blockDim.x + threadIdx.x) >> 3;  // octet id
    const int nq   = (gridDim.x * blockDim.x) >> 3;                  // total octets

    const int is64 = g_is64;
    const float db = g_db;
    const long long* __restrict__ row64 = (const long long*)row_p;
    const long long* __restrict__ col64 = (const long long*)col_p;
    const long long* __restrict__ lab64 = (const long long*)label_p;
    const int* __restrict__ row32 = (const int*)row_p;
    const int* __restrict__ col32 = (const int*)col_p;
    const int* __restrict__ lab32 = (const int*)label_p;

    // warp-uniform trip count over edge pairs (e0 = go + t*2nq, e1 = e0 + nq)
    const int go0   = go - (lane >> 3);
    const int trips = (go0 < n_edges) ? (n_edges - go0 + 2 * nq - 1) / (2 * nq) : 0;

    const __half2 z2 = __floats2half2_rn(0.0f, 0.0f);
    float lsum = 0.0f;

    auto fetch = [&](int e, bool valid, int& ri, int& ci, int& yy) {
        int es = valid ? e : 0;
        if (is64) {
            long long r = row64[es], c = col64[es];
            ri = (int)r; ci = (int)c;
            yy = (lab64[r] == lab64[c]);
        } else {
            ri = row32[es]; ci = col32[es];
            yy = (lab32[ri] == lab32[ci]);
        }
    };

    int e0 = go;
    int e1 = go + nq;
    bool v0 = (e0 < n_edges), v1 = (e1 < n_edges);
    int r0, c0, y0, r1, c1, y1;
    fetch(e0, v0, r0, c0, y0);
    fetch(e1, v1, r1, c1, y1);

    for (int t = 0; t < trips; t++) {
        // prefetch next iteration's indices + labels
        int e0n = e0 + 2 * nq, e1n = e1 + 2 * nq;
        bool v0n = (e0n < n_edges), v1n = (e1n < n_edges);
        int r0n, c0n, y0n, r1n, c1n, y1n;
        fetch(e0n, v0n, r0n, c0n, y0n);
        fetch(e1n, v1n, r1n, c1n, y1n);

        // 8 independent LDG.128: 2 per table per edge
        const uint4* pt0 = (const uint4*)(g_proj + (unsigned)r0 * 256 + hb);
        const uint4* pc0 = (const uint4*)(g_proj + (unsigned)c0 * 256 + 128 + hb);
        const uint4* pt1 = (const uint4*)(g_proj + (unsigned)r1 * 256 + hb);
        const uint4* pc1 = (const uint4*)(g_proj + (unsigned)c1 * 256 + 128 + hb);
        uint4 A0[2] = {pt0[0], pt0[1]};
        uint4 B0[2] = {pc0[0], pc0[1]};
        uint4 A1[2] = {pt1[0], pt1[1]};
        uint4 B1[2] = {pc1[0], pc1[1]};

        float d0 = 0.0f, d1 = 0.0f;
        #pragma unroll
        for (int i = 0; i < 2; i++) {
            const unsigned int a0[4] = {A0[i].x, A0[i].y, A0[i].z, A0[i].w};
            const unsigned int b0[4] = {B0[i].x, B0[i].y, B0[i].z, B0[i].w};
            const unsigned int a1[4] = {A1[i].x, A1[i].y, A1[i].z, A1[i].w};
            const unsigned int b1u[4] = {B1[i].x, B1[i].y, B1[i].z, B1[i].w};
            __half2 acc0 = z2, acc1 = z2;
            #pragma unroll
            for (int j = 0; j < 4; j++) {
                uint2 cd = s_cd[o * 8 + i * 4 + j];
                __half2 wp = u2h2(cd.x), wn = u2h2(cd.y);

                __half2 h0 = __hadd2(u2h2(a0[j]), u2h2(b0[j]));
                acc0 = __hfma2(wp, __hmax2(h0, z2), acc0);
                acc0 = __hfma2(wn, __hmin2(h0, z2), acc0);

                __half2 h1 = __hadd2(u2h2(a1[j]), u2h2(b1u[j]));
                acc1 = __hfma2(wp, __hmax2(h1, z2), acc1);
                acc1 = __hfma2(wn, __hmin2(h1, z2), acc1);
            }
            float2 f0 = __half22float2(acc0);
            float2 f1 = __half22float2(acc1);
            d0 += f0.x + f0.y;
            d1 += f1.x + f1.y;
        }

        // octet reduction (8 lanes per edge)
        #pragma unroll
        for (int off = 1; off < 8; off <<= 1) {
            d0 += __shfl_xor_sync(0xffffffffu, d0, off);
            d1 += __shfl_xor_sync(0xffffffffu, d1, off);
        }
        if (o == 0) {
            if (v0) {
                float d = y0 ? (d0 + db) : -(d0 + db);
                lsum += fmaxf(d, 0.0f) + log1pf(__expf(-fabsf(d)));
            }
            if (v1) {
                float d = y1 ? (d1 + db) : -(d1 + db);
                lsum += fmaxf(d, 0.0f) + log1pf(__expf(-fabsf(d)));
            }
        }

        e0 = e0n; e1 = e1n; v0 = v0n; v1 = v1n;
        r0 = r0n; c0 = c0n; y0 = y0n;
        r1 = r1n; c1 = c1n; y1 = y1n;
    }

    // block reduction (only o==0 lanes hold nonzero lsum)
    #pragma unroll
    for (int off = 16; off > 0; off >>= 1)
        lsum += __shfl_xor_sync(0xffffffffu, lsum, off);

    __shared__ float ssum[8];
    __shared__ bool  s_last;
    const int wid = threadIdx.x >> 5;
    if (lane == 0) ssum[wid] = lsum;
    __syncthreads();
    if (threadIdx.x == 0) {
        float s = 0.0f;
        #pragma unroll
        for (int i = 0; i < 8; i++) s += ssum[i];
        g_partial[blockIdx.x] = s;
        __threadfence();
        unsigned int prev = atomicAdd(&g_done, 1u);
        s_last = (prev == gridDim.x - 1);
    }
    __syncthreads();

    if (s_last) {
        __shared__ double sd[256];
        const volatile float* gp = g_partial;
        double acc = 0.0;
        for (int i = threadIdx.x; i < (int)gridDim.x; i += 256) acc += (double)gp[i];
        sd[threadIdx.x] = acc;
        __syncthreads();
        for (int off = 128; off > 0; off >>= 1) {
            if (threadIdx.x < off) sd[threadIdx.x] += sd[threadIdx.x + off];
            __syncthreads();
        }
        if (threadIdx.x == 0) out[0] = (float)(sd[0] / (double)n_edges);
    }
}

// ---------------------------------------------------------------------------
// Launch. Inputs: feature, W1, b1, alpha, W2, b2, row, col, label
// ---------------------------------------------------------------------------
extern "C" void kernel_launch(void* const* d_in, const int* in_sizes, int n_in,
                              void* d_out, int out_size) {
    const float* feature = (const float*)d_in[0];
    const float* W1      = (const float*)d_in[1];
    const float* b1      = (const float*)d_in[2];
    const float* alpha   = (const float*)d_in[3];
    const float* W2      = (const float*)d_in[4];
    const float* b2      = (const float*)d_in[5];
    const void*  row     = d_in[6];
    const void*  col     = d_in[7];
    const void*  label   = d_in[8];
    float* out = (float*)d_out;

    const int n_nodes = in_sizes[0] / NHID;
    const int n_edges = in_sizes[6];

    const size_t smem = (size_t)(64 * PADH + 128 * PADB) * sizeof(__half);
    cudaFuncSetAttribute(node_proj_kernel,
                         cudaFuncAttributeMaxDynamicSharedMemorySize, (int)smem);

    setup_kernel<<<64, 256>>>((const unsigned int*)row, n_edges, W1, W2, alpha, b2);

    node_proj_kernel<<<(n_nodes + 63) / 64, 256, smem>>>(feature, b1, n_nodes);

    edge_loss_kernel<<<EDGE_GRID, 256>>>(row, col, label, out, n_edges);
}

// round 15
// speedup vs baseline: 3.2674x; 1.1266x over previous
#include <cuda_runtime.h>
#include <cuda_fp16.h>
#include <mma.h>
#include <math.h>

using namespace nvcuda;

#define NHID 128
#define NODE_CAP 100000
#define EDGE_GRID 592

constexpr int PADH = 136;   // half stride for A tile [64][128+8]
constexpr int PADB = 264;   // half stride for B tile [128][256+8]
constexpr int PSTG = 72;    // float stride for 32x64 epilogue staging

// Scratch (device globals; allocation in kernel_launch is forbidden)
// fp8 e4m3 table: g_proj8[n][0:128] = F@W1_top + b1, [128:256] = F@W1_bot
__device__ unsigned char g_proj8[(size_t)NODE_CAP * 256];
__device__ __half g_w1h[128 * 256];   // fp16 W1, concat layout
__device__ float  g_partial[EDGE_GRID];
__device__ uint2  g_cd[64];           // per channel-pair: {half2(wd), half2(alpha*wd)}
__device__ float  g_db;               // b2[0] - b2[1]
__device__ int    g_is64;
__device__ unsigned int g_done;

static __device__ __forceinline__ __half2 u2h2(unsigned int u) {
    __half2 h; *(unsigned int*)&h = u; return h;
}

// Convert 4 packed e4m3 (one 32-bit word) -> two half2 (channels in order)
#define CVT8X4(w, h0, h1)                                              \
    asm("{ .reg .b16 lo, hi;\n\t"                                      \
        "  mov.b32 {lo, hi}, %2;\n\t"                                  \
        "  cvt.rn.f16x2.e4m3x2 %0, lo;\n\t"                            \
        "  cvt.rn.f16x2.e4m3x2 %1, hi; }"                              \
        : "=r"(h0), "=r"(h1) : "r"(w))

// ---------------------------------------------------------------------------
// Kernel 0: setup. Convert W1 -> fp16 concat layout; block 0 also detects
// index dtype, builds edge-phase constants, resets counter.
// ---------------------------------------------------------------------------
__global__ void setup_kernel(const unsigned int* __restrict__ rowp, int n_edges,
                             const float* __restrict__ W1,
                             const float* __restrict__ W2,
                             const float* __restrict__ alpha,
                             const float* __restrict__ b2) {
    const int gid = blockIdx.x * 256 + threadIdx.x;   // [0, 16384)
    const int k   = gid >> 7;
    const int o2  = (gid & 127) * 2;
    float2 f = (o2 < 128) ? *(const float2*)&W1[k * 128 + o2]
                          : *(const float2*)&W1[(128 + k) * 128 + (o2 - 128)];
    *(__half2*)&g_w1h[k * 256 + o2] = __floats2half2_rn(f.x, f.y);

    if (blockIdx.x == 0) {
        int t = threadIdx.x;
        if (t < 64) {
            float wd0 = W2[4 * t + 0] - W2[4 * t + 1];
            float wd1 = W2[4 * t + 2] - W2[4 * t + 3];
            __half2 wp = __floats2half2_rn(wd0, wd1);
            __half2 wn = __floats2half2_rn(alpha[2 * t] * wd0, alpha[2 * t + 1] * wd1);
            uint2 cd;
            cd.x = *(unsigned int*)&wp;
            cd.y = *(unsigned int*)&wn;
            g_cd[t] = cd;
        }
        if (t == 0) {
            g_done = 0u;
            g_db = b2[0] - b2[1];
            int nchk = n_edges >= 64 ? 64 : n_edges;
            int is64 = 1;
            for (int i = 0; i < nchk; i++)
                if (rowp[2 * i + 1] != 0u) { is64 = 0; break; }
            g_is64 = is64;
        }
    }
}

// ---------------------------------------------------------------------------
// Kernel 1: node projections, single pass. Block: 64 nodes x 256 outputs,
// K=128, fp16 WMMA m16n16k16. Epilogue quantizes to fp8 e4m3.
// ---------------------------------------------------------------------------
__global__ void __launch_bounds__(256, 2) node_proj_kernel(
        const float* __restrict__ feature,
        const float* __restrict__ b1,
        int n_nodes) {
    extern __shared__ float sm[];
    __half* Ah = (__half*)sm;             // [64][PADH]
    __half* Bh = Ah + 64 * PADH;          // [128][PADB]

    const int tid   = threadIdx.x;
    const int nbase = blockIdx.x * 64;

    for (int idx = tid; idx < 64 * 64; idx += 256) {
        int r  = idx >> 6;
        int c2 = (idx & 63) * 2;
        int n  = nbase + r;
        float2 fa = (n < n_nodes) ? *(const float2*)&feature[(size_t)n * 128 + c2]
                                  : make_float2(0.0f, 0.0f);
        *(__half2*)&Ah[r * PADH + c2] = __floats2half2_rn(fa.x, fa.y);
    }
    {
        const uint4* src = (const uint4*)g_w1h;
        uint4* dst = (uint4*)Bh;
        for (int idx = tid; idx < 128 * 32; idx += 256) {
            int k  = idx >> 5;
            int cu = idx & 31;
            dst[k * (PADB / 8) + cu] = src[k * 32 + cu];
        }
    }
    __syncthreads();

    const int w    = tid >> 5;
    const int lane = tid & 31;
    const int wm   = w & 1;
    const int wn   = w >> 1;

    wmma::fragment<wmma::accumulator, 16, 16, 16, float> acc[2][4];
    #pragma unroll
    for (int i = 0; i < 2; i++)
        #pragma unroll
        for (int j = 0; j < 4; j++)
            wmma::fill_fragment(acc[i][j], 0.0f);

    #pragma unroll
    for (int k0 = 0; k0 < 128; k0 += 16) {
        wmma::fragment<wmma::matrix_a, 16, 16, 16, __half, wmma::row_major> a[2];
        #pragma unroll
        for (int i = 0; i < 2; i++)
            wmma::load_matrix_sync(a[i], &Ah[(wm * 32 + i * 16) * PADH + k0], PADH);
        #pragma unroll
        for (int j = 0; j < 4; j++) {
            wmma::fragment<wmma::matrix_b, 16, 16, 16, __half, wmma::row_major> b;
            wmma::load_matrix_sync(b, &Bh[k0 * PADB + wn * 64 + j * 16], PADB);
            #pragma unroll
            for (int i = 0; i < 2; i++)
                wmma::mma_sync(acc[i][j], a[i], b, acc[i][j]);
        }
    }

    __syncthreads();

    float* ws = sm + w * (32 * PSTG);
    #pragma unroll
    for (int i = 0; i < 2; i++)
        #pragma unroll
        for (int j = 0; j < 4; j++)
            wmma::store_matrix_sync(&ws[(i * 16) * PSTG + j * 16], acc[i][j],
                                    PSTG, wmma::mem_row_major);
    __syncwarp();

    const int co = lane * 2;
    const int ob = wn * 64 + co;        // channel index in [0,256)
    float2 bv = (ob < 128) ? *(const float2*)&b1[ob] : make_float2(0.0f, 0.0f);

    #pragma unroll 4
    for (int r = 0; r < 32; r++) {
        int n = nbase + wm * 32 + r;
        if (n < n_nodes) {
            float2 f = *(const float2*)&ws[r * PSTG + co];
            float fx = f.x + bv.x;
            float fy = f.y + bv.y;
            unsigned short p8;
            // second source -> low byte (channel ob), first -> high (ob+1)
            asm("cvt.rn.satfinite.e4m3x2.f32 %0, %1, %2;"
                : "=h"(p8) : "f"(fy), "f"(fx));
            *(unsigned short*)&g_proj8[(size_t)n * 256 + ob] = p8;
        }
    }
}

// ---------------------------------------------------------------------------
// Kernel 2: per-edge loss. 8 threads per edge (octet), 4 edges per octet per
// iteration (8 independent LDG.128 per thread-iteration). Thread o handles
// channels [o*16, o*16+16) as fp8 -> 16 B per table per edge. Prefetched
// idx/label pipeline, warp-uniform trips, fp16x2 PReLU-dot, softplus loss,
// last-block final reduction.
// ---------------------------------------------------------------------------
__global__ void __launch_bounds__(256) edge_loss_kernel(
        const void* __restrict__ row_p,
        const void* __restrict__ col_p,
        const void* __restrict__ label_p,
        float* __restrict__ out,
        int n_edges) {
    __shared__ uint2 s_cd[64];
    if (threadIdx.x < 64) s_cd[threadIdx.x] = g_cd[threadIdx.x];
    __syncthreads();

    const int lane = threadIdx.x & 31;
    const int o    = threadIdx.x & 7;          // octet position
    const int bb   = o * 16;                   // channel/byte base
    const int go   = (blockIdx.x * blockDim.x + threadIdx.x) >> 3;  // octet id
    const int nq   = (gridDim.x * blockDim.x) >> 3;                  // total octets

    const int is64 = g_is64;
    const float db = g_db;
    const long long* __restrict__ row64 = (const long long*)row_p;
    const long long* __restrict__ col64 = (const long long*)col_p;
    const long long* __restrict__ lab64 = (const long long*)label_p;
    const int* __restrict__ row32 = (const int*)row_p;
    const int* __restrict__ col32 = (const int*)col_p;
    const int* __restrict__ lab32 = (const int*)label_p;

    // warp-uniform trip count over groups of 4 edges (stride 4*nq)
    const int go0   = go - (lane >> 3);
    const int trips = (go0 < n_edges) ? (n_edges - go0 + 4 * nq - 1) / (4 * nq) : 0;

    const __half2 z2 = __floats2half2_rn(0.0f, 0.0f);
    float lsum = 0.0f;

    auto fetch = [&](int e, bool valid, int& ri, int& ci, int& yy) {
        int es = valid ? e : 0;
        if (is64) {
            long long r = row64[es], c = col64[es];
            ri = (int)r; ci = (int)c;
            yy = (lab64[r] == lab64[c]);
        } else {
            ri = row32[es]; ci = col32[es];
            yy = (lab32[ri] == lab32[ci]);
        }
    };

    int ee[4]; bool vv[4]; int rr[4], cc[4], yy[4];
    #pragma unroll
    for (int u = 0; u < 4; u++) {
        ee[u] = go + u * nq;
        vv[u] = (ee[u] < n_edges);
        fetch(ee[u], vv[u], rr[u], cc[u], yy[u]);
    }

    for (int t = 0; t < trips; t++) {
        // prefetch next iteration's indices + labels
        int en[4]; bool vn[4]; int rn[4], cn[4], yn[4];
        #pragma unroll
        for (int u = 0; u < 4; u++) {
            en[u] = ee[u] + 4 * nq;
            vn[u] = (en[u] < n_edges);
            fetch(en[u], vn[u], rn[u], cn[u], yn[u]);
        }

        // 8 independent 16B gathers: top + bot per edge
        uint4 A[4], B[4];
        #pragma unroll
        for (int u = 0; u < 4; u++) {
            A[u] = *(const uint4*)(g_proj8 + (size_t)(unsigned)rr[u] * 256 + bb);
            B[u] = *(const uint4*)(g_proj8 + (size_t)(unsigned)cc[u] * 256 + 128 + bb);
        }

        float dd[4];
        #pragma unroll
        for (int u = 0; u < 4; u++) {
            const unsigned int aw[4] = {A[u].x, A[u].y, A[u].z, A[u].w};
            const unsigned int bw[4] = {B[u].x, B[u].y, B[u].z, B[u].w};
            __half2 acc = z2;
            #pragma unroll
            for (int j = 0; j < 4; j++) {
                unsigned int a0, a1, b0, b1u;
                CVT8X4(aw[j], a0, a1);
                CVT8X4(bw[j], b0, b1u);
                uint2 cd0 = s_cd[o * 8 + j * 2 + 0];
                uint2 cd1 = s_cd[o * 8 + j * 2 + 1];

                __half2 h0 = __hadd2(u2h2(a0), u2h2(b0));
                acc = __hfma2(u2h2(cd0.x), __hmax2(h0, z2), acc);
                acc = __hfma2(u2h2(cd0.y), __hmin2(h0, z2), acc);

                __half2 h1 = __hadd2(u2h2(a1), u2h2(b1u));
                acc = __hfma2(u2h2(cd1.x), __hmax2(h1, z2), acc);
                acc = __hfma2(u2h2(cd1.y), __hmin2(h1, z2), acc);
            }
            float2 f = __half22float2(acc);
            dd[u] = f.x + f.y;
        }

        // octet reductions (8 lanes per edge)
        #pragma unroll
        for (int off = 1; off < 8; off <<= 1) {
            #pragma unroll
            for (int u = 0; u < 4; u++)
                dd[u] += __shfl_xor_sync(0xffffffffu, dd[u], off);
        }
        if (o == 0) {
            #pragma unroll
            for (int u = 0; u < 4; u++) {
                if (vv[u]) {
                    float d = yy[u] ? (dd[u] + db) : -(dd[u] + db);
                    lsum += fmaxf(d, 0.0f) + log1pf(__expf(-fabsf(d)));
                }
            }
        }

        #pragma unroll
        for (int u = 0; u < 4; u++) {
            ee[u] = en[u]; vv[u] = vn[u];
            rr[u] = rn[u]; cc[u] = cn[u]; yy[u] = yn[u];
        }
    }

    // block reduction (only o==0 lanes hold nonzero lsum)
    #pragma unroll
    for (int off = 16; off > 0; off >>= 1)
        lsum += __shfl_xor_sync(0xffffffffu, lsum, off);

    __shared__ float ssum[8];
    __shared__ bool  s_last;
    const int wid = threadIdx.x >> 5;
    if (lane == 0) ssum[wid] = lsum;
    __syncthreads();
    if (threadIdx.x == 0) {
        float s = 0.0f;
        #pragma unroll
        for (int i = 0; i < 8; i++) s += ssum[i];
        g_partial[blockIdx.x] = s;
        __threadfence();
        unsigned int prev = atomicAdd(&g_done, 1u);
        s_last = (prev == gridDim.x - 1);
    }
    __syncthreads();

    if (s_last) {
        __shared__ double sd[256];
        const volatile float* gp = g_partial;
        double acc = 0.0;
        for (int i = threadIdx.x; i < (int)gridDim.x; i += 256) acc += (double)gp[i];
        sd[threadIdx.x] = acc;
        __syncthreads();
        for (int off = 128; off > 0; off >>= 1) {
            if (threadIdx.x < off) sd[threadIdx.x] += sd[threadIdx.x + off];
            __syncthreads();
        }
        if (threadIdx.x == 0) out[0] = (float)(sd[0] / (double)n_edges);
    }
}

// ---------------------------------------------------------------------------
// Launch. Inputs: feature, W1, b1, alpha, W2, b2, row, col, label
// ---------------------------------------------------------------------------
extern "C" void kernel_launch(void* const* d_in, const int* in_sizes, int n_in,
                              void* d_out, int out_size) {
    const float* feature = (const float*)d_in[0];
    const float* W1      = (const float*)d_in[1];
    const float* b1      = (const float*)d_in[2];
    const float* alpha   = (const float*)d_in[3];
    const float* W2      = (const float*)d_in[4];
    const float* b2      = (const float*)d_in[5];
    const void*  row     = d_in[6];
    const void*  col     = d_in[7];
    const void*  label   = d_in[8];
    float* out = (float*)d_out;

    const int n_nodes = in_sizes[0] / NHID;
    const int n_edges = in_sizes[6];

    const size_t smem = (size_t)(64 * PADH + 128 * PADB) * sizeof(__half);
    cudaFuncSetAttribute(node_proj_kernel,
                         cudaFuncAttributeMaxDynamicSharedMemorySize, (int)smem);

    setup_kernel<<<64, 256>>>((const unsigned int*)row, n_edges, W1, W2, alpha, b2);

    node_proj_kernel<<<(n_nodes + 63) / 64, 256, smem>>>(feature, b1, n_nodes);

    edge_loss_kernel<<<EDGE_GRID, 256>>>(row, col, label, out, n_edges);
}

// round 17
// speedup vs baseline: 3.8738x; 1.1856x over previous
#include <cuda_runtime.h>
#include <cuda_fp16.h>
#include <mma.h>
#include <math.h>

using namespace nvcuda;

#define NHID 128
#define NODE_CAP 100000
#define EDGE_GRID 592

constexpr int PADH = 136;   // half stride for A tile [64][128+8]
constexpr int PADB = 264;   // half stride for B tile [128][256+8]
constexpr int PSTG = 72;    // float stride for 32x64 epilogue staging

// Scratch (device globals; allocation in kernel_launch is forbidden)
// fp8 e4m3 table: g_proj8[n][0:128] = F@W1_top + b1, [128:256] = F@W1_bot
__device__ unsigned char g_proj8[(size_t)NODE_CAP * 256];
__device__ __half g_w1h[128 * 256];   // fp16 W1, concat layout
__device__ float  g_partial[EDGE_GRID];
__device__ uint2  g_cd[64];           // per channel-pair: {half2(wd), half2(alpha*wd)}
__device__ float  g_db;               // b2[0] - b2[1]
__device__ int    g_is64;
__device__ unsigned int g_done;

static __device__ __forceinline__ __half2 u2h2(unsigned int u) {
    __half2 h; *(unsigned int*)&h = u; return h;
}

// Convert 4 packed e4m3 (one 32-bit word) -> two half2 (channels in order)
#define CVT8X4(w, h0, h1)                                              \
    asm("{ .reg .b16 lo, hi;\n\t"                                      \
        "  mov.b32 {lo, hi}, %2;\n\t"                                  \
        "  cvt.rn.f16x2.e4m3x2 %0, lo;\n\t"                            \
        "  cvt.rn.f16x2.e4m3x2 %1, hi; }"                              \
        : "=r"(h0), "=r"(h1) : "r"(w))

// ---------------------------------------------------------------------------
// Kernel 0: setup. Convert W1 -> fp16 concat layout; block 0 also detects
// index dtype, builds edge-phase constants, resets counter.
// ---------------------------------------------------------------------------
__global__ void setup_kernel(const unsigned int* __restrict__ rowp, int n_edges,
                             const float* __restrict__ W1,
                             const float* __restrict__ W2,
                             const float* __restrict__ alpha,
                             const float* __restrict__ b2) {
    const int gid = blockIdx.x * 256 + threadIdx.x;   // [0, 16384)
    const int k   = gid >> 7;
    const int o2  = (gid & 127) * 2;
    float2 f = (o2 < 128) ? *(const float2*)&W1[k * 128 + o2]
                          : *(const float2*)&W1[(128 + k) * 128 + (o2 - 128)];
    *(__half2*)&g_w1h[k * 256 + o2] = __floats2half2_rn(f.x, f.y);

    if (blockIdx.x == 0) {
        int t = threadIdx.x;
        if (t < 64) {
            float wd0 = W2[4 * t + 0] - W2[4 * t + 1];
            float wd1 = W2[4 * t + 2] - W2[4 * t + 3];
            __half2 wp = __floats2half2_rn(wd0, wd1);
            __half2 wn = __floats2half2_rn(alpha[2 * t] * wd0, alpha[2 * t + 1] * wd1);
            uint2 cd;
            cd.x = *(unsigned int*)&wp;
            cd.y = *(unsigned int*)&wn;
            g_cd[t] = cd;
        }
        if (t == 0) {
            g_done = 0u;
            g_db = b2[0] - b2[1];
            int nchk = n_edges >= 64 ? 64 : n_edges;
            int is64 = 1;
            for (int i = 0; i < nchk; i++)
                if (rowp[2 * i + 1] != 0u) { is64 = 0; break; }
            g_is64 = is64;
        }
    }
}

// ---------------------------------------------------------------------------
// Kernel 1: node projections, single pass. Block: 64 nodes x 256 outputs,
// K=128, fp16 WMMA m16n16k16. Epilogue quantizes to fp8 e4m3. (unchanged)
// ---------------------------------------------------------------------------
__global__ void __launch_bounds__(256, 2) node_proj_kernel(
        const float* __restrict__ feature,
        const float* __restrict__ b1,
        int n_nodes) {
    extern __shared__ float sm[];
    __half* Ah = (__half*)sm;             // [64][PADH]
    __half* Bh = Ah + 64 * PADH;          // [128][PADB]

    const int tid   = threadIdx.x;
    const int nbase = blockIdx.x * 64;

    for (int idx = tid; idx < 64 * 64; idx += 256) {
        int r  = idx >> 6;
        int c2 = (idx & 63) * 2;
        int n  = nbase + r;
        float2 fa = (n < n_nodes) ? *(const float2*)&feature[(size_t)n * 128 + c2]
                                  : make_float2(0.0f, 0.0f);
        *(__half2*)&Ah[r * PADH + c2] = __floats2half2_rn(fa.x, fa.y);
    }
    {
        const uint4* src = (const uint4*)g_w1h;
        uint4* dst = (uint4*)Bh;
        for (int idx = tid; idx < 128 * 32; idx += 256) {
            int k  = idx >> 5;
            int cu = idx & 31;
            dst[k * (PADB / 8) + cu] = src[k * 32 + cu];
        }
    }
    __syncthreads();

    const int w    = tid >> 5;
    const int lane = tid & 31;
    const int wm   = w & 1;
    const int wn   = w >> 1;

    wmma::fragment<wmma::accumulator, 16, 16, 16, float> acc[2][4];
    #pragma unroll
    for (int i = 0; i < 2; i++)
        #pragma unroll
        for (int j = 0; j < 4; j++)
            wmma::fill_fragment(acc[i][j], 0.0f);

    #pragma unroll
    for (int k0 = 0; k0 < 128; k0 += 16) {
        wmma::fragment<wmma::matrix_a, 16, 16, 16, __half, wmma::row_major> a[2];
        #pragma unroll
        for (int i = 0; i < 2; i++)
            wmma::load_matrix_sync(a[i], &Ah[(wm * 32 + i * 16) * PADH + k0], PADH);
        #pragma unroll
        for (int j = 0; j < 4; j++) {
            wmma::fragment<wmma::matrix_b, 16, 16, 16, __half, wmma::row_major> b;
            wmma::load_matrix_sync(b, &Bh[k0 * PADB + wn * 64 + j * 16], PADB);
            #pragma unroll
            for (int i = 0; i < 2; i++)
                wmma::mma_sync(acc[i][j], a[i], b, acc[i][j]);
        }
    }

    __syncthreads();

    float* ws = sm + w * (32 * PSTG);
    #pragma unroll
    for (int i = 0; i < 2; i++)
        #pragma unroll
        for (int j = 0; j < 4; j++)
            wmma::store_matrix_sync(&ws[(i * 16) * PSTG + j * 16], acc[i][j],
                                    PSTG, wmma::mem_row_major);
    __syncwarp();

    const int co = lane * 2;
    const int ob = wn * 64 + co;        // channel index in [0,256)
    float2 bv = (ob < 128) ? *(const float2*)&b1[ob] : make_float2(0.0f, 0.0f);

    #pragma unroll 4
    for (int r = 0; r < 32; r++) {
        int n = nbase + wm * 32 + r;
        if (n < n_nodes) {
            float2 f = *(const float2*)&ws[r * PSTG + co];
            float fx = f.x + bv.x;
            float fy = f.y + bv.y;
            unsigned short p8;
            asm("cvt.rn.satfinite.e4m3x2.f32 %0, %1, %2;"
                : "=h"(p8) : "f"(fy), "f"(fx));
            *(unsigned short*)&g_proj8[(size_t)n * 256 + ob] = p8;
        }
    }
}

// ---------------------------------------------------------------------------
// Kernel 2: per-edge loss. 8 threads per edge (octet), 4 edges per octet per
// iteration. Lane-specialized fetch: thread o<4 loads edge u=o's row/col/label
// ONCE; shfl broadcasts distribute (r,c,y) octet-wide (replaces 8x-redundant
// scalar loads). 8 independent 16B table gathers per thread per iteration.
// fp8->fp16 convert, PReLU-dot, softplus loss, last-block final reduction.
// ---------------------------------------------------------------------------
__global__ void __launch_bounds__(256) edge_loss_kernel(
        const void* __restrict__ row_p,
        const void* __restrict__ col_p,
        const void* __restrict__ label_p,
        float* __restrict__ out,
        int n_edges) {
    __shared__ uint2 s_cd[64];
    if (threadIdx.x < 64) s_cd[threadIdx.x] = g_cd[threadIdx.x];
    __syncthreads();

    const int lane = threadIdx.x & 31;
    const int o    = threadIdx.x & 7;          // octet position
    const int bb   = o * 16;                   // channel/byte base
    const int go   = (blockIdx.x * blockDim.x + threadIdx.x) >> 3;  // octet id
    const int nq   = (gridDim.x * blockDim.x) >> 3;                  // total octets

    const int is64 = g_is64;
    const float db = g_db;
    const long long* __restrict__ row64 = (const long long*)row_p;
    const long long* __restrict__ col64 = (const long long*)col_p;
    const long long* __restrict__ lab64 = (const long long*)label_p;
    const int* __restrict__ row32 = (const int*)row_p;
    const int* __restrict__ col32 = (const int*)col_p;
    const int* __restrict__ lab32 = (const int*)label_p;

    // warp-uniform trip count over groups of 4 edges (stride 4*nq)
    const int go0   = go - (lane >> 3);
    const int trips = (go0 < n_edges) ? (n_edges - go0 + 4 * nq - 1) / (4 * nq) : 0;

    const __half2 z2 = __floats2half2_rn(0.0f, 0.0f);
    float lsum = 0.0f;

    // own-edge fetch (only meaningful for o < 4)
    auto fetch_own = [&](int e, int& ri, int& ci, int& yi) {
        int es = (o < 4 && e < n_edges) ? e : 0;
        if (is64) {
            long long r = row64[es], c = col64[es];
            ri = (int)r; ci = (int)c;
            yi = (lab64[r] == lab64[c]);
        } else {
            ri = row32[es]; ci = col32[es];
            yi = (lab32[ri] == lab32[ci]);
        }
    };

    // per-edge indices for validity (arithmetic only)
    int eu[4];
    #pragma unroll
    for (int u = 0; u < 4; u++) eu[u] = go + u * nq;

    int e_own = go + o * nq;
    int ro, co_, yo;
    fetch_own(e_own, ro, co_, yo);

    int rr[4], cc[4], yy[4];
    #pragma unroll
    for (int u = 0; u < 4; u++) {
        rr[u] = __shfl_sync(0xffffffffu, ro,  u, 8);
        cc[u] = __shfl_sync(0xffffffffu, co_, u, 8);
        yy[u] = __shfl_sync(0xffffffffu, yo,  u, 8);
    }

    for (int t = 0; t < trips; t++) {
        // prefetch own next edge (loads overlap with this iteration's compute)
        int e_next = e_own + 4 * nq;
        int ron, con, yon;
        fetch_own(e_next, ron, con, yon);

        // 8 independent 16B gathers: top + bot per edge
        uint4 A[4], B[4];
        #pragma unroll
        for (int u = 0; u < 4; u++) {
            A[u] = *(const uint4*)(g_proj8 + (size_t)(unsigned)rr[u] * 256 + bb);
            B[u] = *(const uint4*)(g_proj8 + (size_t)(unsigned)cc[u] * 256 + 128 + bb);
        }

        float dd[4];
        #pragma unroll
        for (int u = 0; u < 4; u++) {
            const unsigned int aw[4] = {A[u].x, A[u].y, A[u].z, A[u].w};
            const unsigned int bw[4] = {B[u].x, B[u].y, B[u].z, B[u].w};
            __half2 acc = z2;
            #pragma unroll
            for (int j = 0; j < 4; j++) {
                unsigned int a0, a1, b0, b1u;
                CVT8X4(aw[j], a0, a1);
                CVT8X4(bw[j], b0, b1u);
                uint2 cd0 = s_cd[o * 8 + j * 2 + 0];
                uint2 cd1 = s_cd[o * 8 + j * 2 + 1];

                __half2 h0 = __hadd2(u2h2(a0), u2h2(b0));
                acc = __hfma2(u2h2(cd0.x), __hmax2(h0, z2), acc);
                acc = __hfma2(u2h2(cd0.y), __hmin2(h0, z2), acc);

                __half2 h1 = __hadd2(u2h2(a1), u2h2(b1u));
                acc = __hfma2(u2h2(cd1.x), __hmax2(h1, z2), acc);
                acc = __hfma2(u2h2(cd1.y), __hmin2(h1, z2), acc);
            }
            float2 f = __half22float2(acc);
            dd[u] = f.x + f.y;
        }

        // octet reductions (8 lanes per edge)
        #pragma unroll
        for (int off = 1; off < 8; off <<= 1) {
            #pragma unroll
            for (int u = 0; u < 4; u++)
                dd[u] += __shfl_xor_sync(0xffffffffu, dd[u], off);
        }
        if (o == 0) {
            #pragma unroll
            for (int u = 0; u < 4; u++) {
                if (eu[u] < n_edges) {
                    float d = yy[u] ? (dd[u] + db) : -(dd[u] + db);
                    lsum += fmaxf(d, 0.0f) + log1pf(__expf(-fabsf(d)));
                }
            }
        }

        // broadcast next iteration's (r,c,y); advance edge indices
        #pragma unroll
        for (int u = 0; u < 4; u++) {
            rr[u] = __shfl_sync(0xffffffffu, ron, u, 8);
            cc[u] = __shfl_sync(0xffffffffu, con, u, 8);
            yy[u] = __shfl_sync(0xffffffffu, yon, u, 8);
            eu[u] += 4 * nq;
        }
        e_own = e_next;
    }

    // block reduction (only o==0 lanes hold nonzero lsum)
    #pragma unroll
    for (int off = 16; off > 0; off >>= 1)
        lsum += __shfl_xor_sync(0xffffffffu, lsum, off);

    __shared__ float ssum[8];
    __shared__ bool  s_last;
    const int wid = threadIdx.x >> 5;
    if (lane == 0) ssum[wid] = lsum;
    __syncthreads();
    if (threadIdx.x == 0) {
        float s = 0.0f;
        #pragma unroll
        for (int i = 0; i < 8; i++) s += ssum[i];
        g_partial[blockIdx.x] = s;
        __threadfence();
        unsigned int prev = atomicAdd(&g_done, 1u);
        s_last = (prev == gridDim.x - 1);
    }
    __syncthreads();

    if (s_last) {
        __shared__ double sd[256];
        const volatile float* gp = g_partial;
        double acc = 0.0;
        for (int i = threadIdx.x; i < (int)gridDim.x; i += 256) acc += (double)gp[i];
        sd[threadIdx.x] = acc;
        __syncthreads();
        for (int off = 128; off > 0; off >>= 1) {
            if (threadIdx.x < off) sd[threadIdx.x] += sd[threadIdx.x + off];
            __syncthreads();
        }
        if (threadIdx.x == 0) out[0] = (float)(sd[0] / (double)n_edges);
    }
}

// ---------------------------------------------------------------------------
// Launch. Inputs: feature, W1, b1, alpha, W2, b2, row, col, label
// ---------------------------------------------------------------------------
extern "C" void kernel_launch(void* const* d_in, const int* in_sizes, int n_in,
                              void* d_out, int out_size) {
    const float* feature = (const float*)d_in[0];
    const float* W1      = (const float*)d_in[1];
    const float* b1      = (const float*)d_in[2];
    const float* alpha   = (const float*)d_in[3];
    const float* W2      = (const float*)d_in[4];
    const float* b2      = (const float*)d_in[5];
    const void*  row     = d_in[6];
    const void*  col     = d_in[7];
    const void*  label   = d_in[8];
    float* out = (float*)d_out;

    const int n_nodes = in_sizes[0] / NHID;
    const int n_edges = in_sizes[6];

    const size_t smem = (size_t)(64 * PADH + 128 * PADB) * sizeof(__half);
    cudaFuncSetAttribute(node_proj_kernel,
                         cudaFuncAttributeMaxDynamicSharedMemorySize, (int)smem);

    setup_kernel<<<64, 256>>>((const unsigned int*)row, n_edges, W1, W2, alpha, b2);

    node_proj_kernel<<<(n_nodes + 63) / 64, 256, smem>>>(feature, b1, n_nodes);

    edge_loss_kernel<<<EDGE_GRID, 256>>>(row, col, label, out, n_edges);
}